// round 2
// baseline (speedup 1.0000x reference)
#include <cuda_runtime.h>

#define N_NODES 16384
#define KNB 32
#define DIN 256
#define DOUT 256
#define DCAT 512
#define EPSBN 1e-5f

// ---------------- scratch (static __device__, no allocs) ----------------
__device__ float d_M[DIN * DIN];        // t-weights: t = x @ M^T
__device__ float d_tb[DIN];             // t bias
__device__ float d_v[DIN];              // ebias vector
__device__ float d_c0[1];               // ebias const
__device__ float d_W2[DOUT * DOUT];     // Wno @ Wv
__device__ float d_b2[DOUT];            // Wno@bv + bno
__device__ float d_ts[N_NODES * DIN];   // t per node
__device__ float d_c[N_NODES * DIN];    // attention-weighted neighbor sum
__device__ float d_outcat[N_NODES * DCAT]; // [self_out | neigh_out]
__device__ float d_part[128 * 1024];    // BN partial sums (deterministic 2-pass)
__device__ float d_scale[DCAT];         // gamma * invstd
__device__ float d_shift[DCAT];         // beta - mean*scale

// ---------------- K0: weight composition + small vectors ----------------
__global__ void precompute_kernel(
    const float* __restrict__ Wq, const float* __restrict__ bq,
    const float* __restrict__ Wk, const float* __restrict__ bk,
    const float* __restrict__ Wv, const float* __restrict__ bv,
    const float* __restrict__ Wno, const float* __restrict__ bno)
{
    const int t = threadIdx.x;
    const int j = blockIdx.x;
    if (blockIdx.y == 0) {
        // M[j][t] = sum_o Wk[o][j] * Wq[o][t]
        float acc = 0.f;
        #pragma unroll 4
        for (int o = 0; o < DOUT; o++) acc = fmaf(Wk[o * DIN + j], Wq[o * DIN + t], acc);
        d_M[j * DIN + t] = acc;
    } else if (blockIdx.y == 1) {
        // W2[j][t] = sum_d Wno[j][d] * Wv[d][t]
        float acc = 0.f;
        #pragma unroll 4
        for (int d = 0; d < DOUT; d++) acc = fmaf(Wno[j * DOUT + d], Wv[d * DIN + t], acc);
        d_W2[j * DOUT + t] = acc;
    } else if (blockIdx.x == 0) {
        float tb = 0.f, vv = 0.f, b2 = 0.f;
        for (int o = 0; o < DOUT; o++) {
            tb = fmaf(Wk[o * DIN + t], bq[o], tb);
            vv = fmaf(bk[o], Wq[o * DIN + t], vv);
        }
        for (int d = 0; d < DOUT; d++) b2 = fmaf(Wno[t * DOUT + d], bv[d], b2);
        d_tb[t] = tb;
        d_v[t]  = vv;
        d_b2[t] = b2 + bno[t];
        if (t == 0) {
            float c = 0.f;
            for (int o = 0; o < DOUT; o++) c = fmaf(bk[o], bq[o], c);
            d_c0[0] = c;
        }
    }
}

// ---------------- SGEMM: C[M,N] = A[M,K] @ B[N,K]^T + bias ----------------
// BM=128, BN=64, BK=16, 256 threads, 8x4 per-thread tile.
// MODE 0: plain + bias. MODE 1: fused gate epilogue:
//   out = relu(acc+bias) * relu(oc*scale + shift)
template <int MODE>
__global__ __launch_bounds__(256, 2) void sgemm_kernel(
    const float* __restrict__ A, int lda,
    const float* __restrict__ B, int ldb,
    const float* __restrict__ bias,
    float* __restrict__ C, int ldc,
    int Kdim,
    const float* __restrict__ oc,
    const float* __restrict__ scale,
    const float* __restrict__ shift)
{
    __shared__ __align__(16) float As[16][128];
    __shared__ __align__(16) float Bs[16][64];

    const int tid = threadIdx.x;
    const int m0 = blockIdx.y * 128;
    const int n0 = blockIdx.x * 64;
    const int tx = tid & 15;
    const int ty = tid >> 4;
    const int ar = tid >> 2;          // 0..63
    const int ak = (tid & 3) << 2;    // 0,4,8,12

    float acc[8][4];
    #pragma unroll
    for (int i = 0; i < 8; i++)
        #pragma unroll
        for (int j = 0; j < 4; j++) acc[i][j] = 0.f;

    const float* Aptr = A + (size_t)(m0 + ar) * lda + ak;
    const float* Bptr = B + (size_t)(n0 + ar) * ldb + ak;

    for (int k0 = 0; k0 < Kdim; k0 += 16) {
        float4 a0 = *(const float4*)(Aptr + k0);
        float4 a1 = *(const float4*)(Aptr + (size_t)64 * lda + k0);
        float4 b0 = *(const float4*)(Bptr + k0);
        As[ak + 0][ar] = a0.x; As[ak + 1][ar] = a0.y;
        As[ak + 2][ar] = a0.z; As[ak + 3][ar] = a0.w;
        As[ak + 0][ar + 64] = a1.x; As[ak + 1][ar + 64] = a1.y;
        As[ak + 2][ar + 64] = a1.z; As[ak + 3][ar + 64] = a1.w;
        Bs[ak + 0][ar] = b0.x; Bs[ak + 1][ar] = b0.y;
        Bs[ak + 2][ar] = b0.z; Bs[ak + 3][ar] = b0.w;
        __syncthreads();
        #pragma unroll
        for (int kk = 0; kk < 16; kk++) {
            float a[8], b[4];
            *(float4*)&a[0] = *(const float4*)&As[kk][ty * 8];
            *(float4*)&a[4] = *(const float4*)&As[kk][ty * 8 + 4];
            *(float4*)&b[0] = *(const float4*)&Bs[kk][tx * 4];
            #pragma unroll
            for (int i = 0; i < 8; i++)
                #pragma unroll
                for (int j = 0; j < 4; j++)
                    acc[i][j] = fmaf(a[i], b[j], acc[i][j]);
        }
        __syncthreads();
    }

    float bb[4];
    #pragma unroll
    for (int j = 0; j < 4; j++) bb[j] = bias[n0 + tx * 4 + j];

    if (MODE == 0) {
        #pragma unroll
        for (int i = 0; i < 8; i++) {
            int row = m0 + ty * 8 + i;
            float4 o;
            o.x = acc[i][0] + bb[0];
            o.y = acc[i][1] + bb[1];
            o.z = acc[i][2] + bb[2];
            o.w = acc[i][3] + bb[3];
            *(float4*)&C[(size_t)row * ldc + n0 + tx * 4] = o;
        }
    } else {
        float sc[4], sh[4];
        #pragma unroll
        for (int j = 0; j < 4; j++) {
            sc[j] = scale[n0 + tx * 4 + j];
            sh[j] = shift[n0 + tx * 4 + j];
        }
        #pragma unroll
        for (int i = 0; i < 8; i++) {
            int row = m0 + ty * 8 + i;
            float4 ov = *(const float4*)&oc[(size_t)row * ldc + n0 + tx * 4];
            float o4[4] = {ov.x, ov.y, ov.z, ov.w};
            float4 r;
            float* rp = &r.x;
            #pragma unroll
            for (int j = 0; j < 4; j++) {
                float g = fmaxf(acc[i][j] + bb[j], 0.f);
                float bn = fmaf(o4[j], sc[j], sh[j]);
                rp[j] = g * fmaxf(bn, 0.f);
            }
            *(float4*)&C[(size_t)row * ldc + n0 + tx * 4] = r;
        }
    }
}

// ---------------- K2: per-node attention (neighbors read ONCE) ----------------
__global__ __launch_bounds__(256) void attn_kernel(
    const float* __restrict__ x, const float* __restrict__ nb)
{
    __shared__ __align__(16) float Xs[KNB * DIN];  // 32 KB
    __shared__ float tsm[DIN];
    __shared__ float es[KNB], sx[KNB], att[KNB];
    __shared__ float red[8];
    __shared__ float s_eb;

    const int n = blockIdx.x;
    const int t = threadIdx.x;
    const int w = t >> 5, l = t & 31;

    // load neighbor tile [32,256] -> smem (float4, coalesced)
    const float4* nb4 = (const float4*)(nb + (size_t)n * KNB * DIN);
    float4* Xs4 = (float4*)Xs;
    #pragma unroll
    for (int j = 0; j < 8; j++) Xs4[t + j * 256] = nb4[t + j * 256];
    tsm[t] = d_ts[(size_t)n * DIN + t];

    // ebias = x_n . v + c0
    float eb = x[(size_t)n * DIN + t] * d_v[t];
    #pragma unroll
    for (int off = 16; off > 0; off >>= 1) eb += __shfl_down_sync(0xffffffffu, eb, off);
    if (l == 0) red[w] = eb;
    __syncthreads();
    if (t == 0) {
        float s = 0.f;
        #pragma unroll
        for (int ww = 0; ww < 8; ww++) s += red[ww];
        s_eb = s + d_c0[0];
    }

    // energies: warp w handles k = w*4 .. w*4+3
    #pragma unroll
    for (int r = 0; r < 4; r++) {
        int k = w * 4 + r;
        const float* xr = &Xs[k * DIN];
        float e = 0.f, s = 0.f;
        #pragma unroll
        for (int j = 0; j < 8; j++) {
            float vx = xr[l + 32 * j];
            e = fmaf(vx, tsm[l + 32 * j], e);
            s += vx;
        }
        #pragma unroll
        for (int off = 16; off > 0; off >>= 1) {
            e += __shfl_down_sync(0xffffffffu, e, off);
            s += __shfl_down_sync(0xffffffffu, s, off);
        }
        if (l == 0) { es[k] = e; sx[k] = s; }
    }
    __syncthreads();

    // softmax over K=32 in warp 0 (masked rows -> 1e-12 pre-softmax)
    if (t < 32) {
        float e = (sx[t] == 0.0f) ? 1e-12f : (es[t] + s_eb);
        float m = e;
        #pragma unroll
        for (int off = 16; off > 0; off >>= 1) m = fmaxf(m, __shfl_xor_sync(0xffffffffu, m, off));
        float p = __expf(e - m);
        float s = p;
        #pragma unroll
        for (int off = 16; off > 0; off >>= 1) s += __shfl_xor_sync(0xffffffffu, s, off);
        att[t] = p / s;
    }
    __syncthreads();

    // c_n = sum_k att[k] * x_nk  (smem reuse: neighbors read 2nd time from smem)
    float accv = 0.f;
    #pragma unroll
    for (int k = 0; k < KNB; k++) accv = fmaf(att[k], Xs[k * DIN + t], accv);
    d_c[(size_t)n * DIN + t] = accv;
}

// ---------------- BN: deterministic two-pass stats ----------------
__global__ void bn_reduce_kernel()
{
    const int t = threadIdx.x;   // 256
    const int b = blockIdx.x;    // 128 blocks x 128 rows
    float s0 = 0.f, q0 = 0.f, s1 = 0.f, q1 = 0.f;
    for (int r = 0; r < 128; r++) {
        size_t row = (size_t)(b * 128 + r);
        float v0 = d_outcat[row * DCAT + t];
        float v1 = d_outcat[row * DCAT + t + 256];
        s0 += v0; q0 = fmaf(v0, v0, q0);
        s1 += v1; q1 = fmaf(v1, v1, q1);
    }
    d_part[b * 1024 + t]       = s0;
    d_part[b * 1024 + t + 256] = s1;
    d_part[b * 1024 + 512 + t]       = q0;
    d_part[b * 1024 + 512 + t + 256] = q1;
}

__global__ void bn_finalize_kernel(const float* __restrict__ gamma,
                                   const float* __restrict__ beta)
{
    const int c = blockIdx.x * 256 + threadIdx.x;  // 512 channels
    float s = 0.f, q = 0.f;
    for (int p = 0; p < 128; p++) {
        s += d_part[p * 1024 + c];
        q += d_part[p * 1024 + 512 + c];
    }
    const float invN = 1.0f / (float)N_NODES;
    float mean = s * invN;
    float var  = q * invN - mean * mean;
    float inv  = rsqrtf(var + EPSBN);
    float scl  = gamma[c] * inv;
    d_scale[c] = scl;
    d_shift[c] = beta[c] - mean * scl;
}

// ---------------- launch ----------------
extern "C" void kernel_launch(void* const* d_in, const int* in_sizes, int n_in,
                              void* d_out, int out_size)
{
    const float* x    = (const float*)d_in[0];
    const float* nb   = (const float*)d_in[1];
    const float* Wq   = (const float*)d_in[2];
    const float* bq   = (const float*)d_in[3];
    const float* Wk   = (const float*)d_in[4];
    const float* bk   = (const float*)d_in[5];
    const float* Wv   = (const float*)d_in[6];
    const float* bv   = (const float*)d_in[7];
    const float* Wno  = (const float*)d_in[8];
    const float* bno  = (const float*)d_in[9];
    const float* Wio  = (const float*)d_in[10];
    const float* bio  = (const float*)d_in[11];
    const float* Wg   = (const float*)d_in[12];
    const float* bg   = (const float*)d_in[13];
    const float* gamma= (const float*)d_in[14];
    const float* beta = (const float*)d_in[15];
    float* out = (float*)d_out;

    float *pM, *ptb, *pW2, *pb2, *pts, *pc, *poc, *pscale, *pshift;
    cudaGetSymbolAddress((void**)&pM,  d_M);
    cudaGetSymbolAddress((void**)&ptb, d_tb);
    cudaGetSymbolAddress((void**)&pW2, d_W2);
    cudaGetSymbolAddress((void**)&pb2, d_b2);
    cudaGetSymbolAddress((void**)&pts, d_ts);
    cudaGetSymbolAddress((void**)&pc,  d_c);
    cudaGetSymbolAddress((void**)&poc, d_outcat);
    cudaGetSymbolAddress((void**)&pscale, d_scale);
    cudaGetSymbolAddress((void**)&pshift, d_shift);

    // K0: compose M = Wk^T Wq, W2 = Wno Wv, bias vectors
    precompute_kernel<<<dim3(256, 3), 256>>>(Wq, bq, Wk, bk, Wv, bv, Wno, bno);

    // G1: ts = x @ M^T + tb           [N,256]
    sgemm_kernel<0><<<dim3(4, 128), 256>>>(x, DIN, pM, DIN, ptb, pts, DIN, DIN,
                                           nullptr, nullptr, nullptr);
    // G2: self_out = x @ Wio^T + bio  -> outcat[:, 0:256]
    sgemm_kernel<0><<<dim3(4, 128), 256>>>(x, DIN, Wio, DIN, bio, poc, DCAT, DIN,
                                           nullptr, nullptr, nullptr);
    // K2: attention -> c (neighbors streamed once through smem)
    attn_kernel<<<N_NODES, 256>>>(x, nb);

    // G3: neigh_out = c @ W2^T + b2   -> outcat[:, 256:512]
    sgemm_kernel<0><<<dim3(4, 128), 256>>>(pc, DIN, pW2, DOUT, pb2, poc + DOUT, DCAT, DOUT,
                                           nullptr, nullptr, nullptr);

    // BN stats (deterministic)
    bn_reduce_kernel<<<128, 256>>>();
    bn_finalize_kernel<<<2, 256>>>(gamma, beta);

    // G4: gate GEMM + fused BN/gate epilogue -> d_out
    sgemm_kernel<1><<<dim3(8, 128), 256>>>(poc, DCAT, Wg, DCAT, bg, out, DCAT, DCAT,
                                           poc, pscale, pshift);
}

// round 5
// speedup vs baseline: 1.5613x; 1.5613x over previous
#include <cuda_runtime.h>
#include <cuda_bf16.h>
#include <cstdint>

#define N_NODES 16384
#define KNB 32
#define DIN 256
#define DOUT 256
#define DCAT 512
#define EPSBN 1e-5f

// ---------------- scratch (static __device__, no allocs) ----------------
__device__ float d_M[DIN * DIN];
__device__ float d_tb[DIN];
__device__ float d_v[DIN];
__device__ float d_c0[1];
__device__ float d_W2[DOUT * DOUT];
__device__ float d_b2[DOUT];
__device__ float d_ts[N_NODES * DIN];
__device__ float d_c[N_NODES * DIN];
__device__ float d_outcat[N_NODES * DCAT];
__device__ float d_part[128 * 1024];
__device__ float d_scale[DCAT];
__device__ float d_shift[DCAT];

// ---------------- helpers ----------------
__device__ __forceinline__ uint32_t smem_u32(const void* p) {
    uint32_t a;
    asm("{ .reg .u64 t; cvta.to.shared.u64 t, %1; cvt.u32.u64 %0, t; }" : "=r"(a) : "l"(p));
    return a;
}
__device__ __forceinline__ void ldsm_x4(uint32_t addr, uint32_t& r0, uint32_t& r1,
                                        uint32_t& r2, uint32_t& r3) {
    asm volatile("ldmatrix.sync.aligned.m8n8.x4.shared.b16 {%0,%1,%2,%3}, [%4];"
                 : "=r"(r0), "=r"(r1), "=r"(r2), "=r"(r3) : "r"(addr));
}
__device__ __forceinline__ void mma16816(float* c, const uint32_t* a, const uint32_t* b) {
    asm volatile(
        "mma.sync.aligned.m16n8k16.row.col.f32.bf16.bf16.f32 "
        "{%0,%1,%2,%3}, {%4,%5,%6,%7}, {%8,%9}, {%0,%1,%2,%3};"
        : "+f"(c[0]), "+f"(c[1]), "+f"(c[2]), "+f"(c[3])
        : "r"(a[0]), "r"(a[1]), "r"(a[2]), "r"(a[3]), "r"(b[0]), "r"(b[1]));
}
__device__ __forceinline__ uint32_t pack_bf16(__nv_bfloat16 lo, __nv_bfloat16 hi) {
    return ((uint32_t)__bfloat16_as_ushort(hi) << 16) | (uint32_t)__bfloat16_as_ushort(lo);
}
// 4 fp32 -> hi uint2 (4 bf16), lo uint2 (4 bf16 residuals)
__device__ __forceinline__ void split4(float4 v, uint2& hi, uint2& lo) {
    __nv_bfloat16 hx = __float2bfloat16(v.x);
    __nv_bfloat16 hy = __float2bfloat16(v.y);
    __nv_bfloat16 hz = __float2bfloat16(v.z);
    __nv_bfloat16 hw = __float2bfloat16(v.w);
    __nv_bfloat16 lx = __float2bfloat16(v.x - __bfloat162float(hx));
    __nv_bfloat16 ly = __float2bfloat16(v.y - __bfloat162float(hy));
    __nv_bfloat16 lz = __float2bfloat16(v.z - __bfloat162float(hz));
    __nv_bfloat16 lw = __float2bfloat16(v.w - __bfloat162float(hw));
    hi.x = pack_bf16(hx, hy); hi.y = pack_bf16(hz, hw);
    lo.x = pack_bf16(lx, ly); lo.y = pack_bf16(lz, lw);
}

// ---------------- K0: weight composition ----------------
__global__ void precompute_kernel(
    const float* __restrict__ Wq, const float* __restrict__ bq,
    const float* __restrict__ Wk, const float* __restrict__ bk,
    const float* __restrict__ Wv, const float* __restrict__ bv,
    const float* __restrict__ Wno, const float* __restrict__ bno)
{
    const int t = threadIdx.x;
    const int j = blockIdx.x;
    if (blockIdx.y == 0) {
        float acc = 0.f;
        #pragma unroll 4
        for (int o = 0; o < DOUT; o++) acc = fmaf(Wk[o * DIN + j], Wq[o * DIN + t], acc);
        d_M[j * DIN + t] = acc;
    } else if (blockIdx.y == 1) {
        float acc = 0.f;
        #pragma unroll 4
        for (int d = 0; d < DOUT; d++) acc = fmaf(Wno[j * DOUT + d], Wv[d * DIN + t], acc);
        d_W2[j * DOUT + t] = acc;
    } else if (blockIdx.x == 0) {
        float tb = 0.f, vv = 0.f, b2 = 0.f;
        for (int o = 0; o < DOUT; o++) {
            tb = fmaf(Wk[o * DIN + t], bq[o], tb);
            vv = fmaf(bk[o], Wq[o * DIN + t], vv);
        }
        for (int d = 0; d < DOUT; d++) b2 = fmaf(Wno[t * DOUT + d], bv[d], b2);
        d_tb[t] = tb;
        d_v[t]  = vv;
        d_b2[t] = b2 + bno[t];
        if (t == 0) {
            float c = 0.f;
            for (int o = 0; o < DOUT; o++) c = fmaf(bk[o], bq[o], c);
            d_c0[0] = c;
        }
    }
}

// ============ bf16x2-split tensor-core GEMM (mma.sync) ============
// C[M,N] = A[M,K] @ B[N,K]^T + bias  (MODE 0)
//        = relu(acc+bias) * relu(oc*scale+shift)  (MODE 1)
// BM=128, BN=128, K chunk 32 fp32. 8 warps, warp tile 64x32.
// bf16 tiles in smem with 80B row stride -> conflict-free ldmatrix.
static constexpr int T_AH = 0;
static constexpr int T_AL = 10240;
static constexpr int T_BH = 20480;
static constexpr int T_BL = 30720;
static constexpr int SMEM_GEMM = 40960;

template <int MODE>
__global__ __launch_bounds__(256, 2) void tc_gemm(
    const float* __restrict__ A, int lda,
    const float* __restrict__ B, int ldb,
    const float* __restrict__ bias,
    float* __restrict__ C, int ldc, int Kdim,
    const float* __restrict__ oc,
    const float* __restrict__ scale,
    const float* __restrict__ shift)
{
    extern __shared__ char smem[];
    const uint32_t sb = smem_u32(smem);
    const int tid = threadIdx.x;
    const int wid = tid >> 5, lane = tid & 31;
    const int m0 = blockIdx.y * 128;
    const int n0 = blockIdx.x * 128;
    const int wm = (wid & 1) * 64;
    const int wn = (wid >> 1) * 32;

    float acc[4][4][4];
    #pragma unroll
    for (int i = 0; i < 4; i++)
        #pragma unroll
        for (int j = 0; j < 4; j++)
            #pragma unroll
            for (int q = 0; q < 4; q++) acc[i][j][q] = 0.f;

    const int r  = tid >> 1;          // 0..127
    const int kh = (tid & 1) * 16;    // col half within chunk

    for (int kc = 0; kc < Kdim; kc += 32) {
        // ---- load + split A[128x32], B[128x32] ----
        {
            const float4* gp = (const float4*)(A + (size_t)(m0 + r) * lda + kc + kh);
            char* rowH = smem + T_AH + r * 80;
            char* rowL = smem + T_AL + r * 80;
            #pragma unroll
            for (int q = 0; q < 4; q++) {
                uint2 h, l;
                split4(gp[q], h, l);
                const int kk = kh + q * 4;
                *(uint2*)(rowH + kk * 2) = h;
                *(uint2*)(rowL + kk * 2) = l;
            }
        }
        {
            const float4* gp = (const float4*)(B + (size_t)(n0 + r) * ldb + kc + kh);
            char* rowH = smem + T_BH + r * 80;
            char* rowL = smem + T_BL + r * 80;
            #pragma unroll
            for (int q = 0; q < 4; q++) {
                uint2 h, l;
                split4(gp[q], h, l);
                const int kk = kh + q * 4;
                *(uint2*)(rowH + kk * 2) = h;
                *(uint2*)(rowL + kk * 2) = l;
            }
        }
        __syncthreads();

        // ---- virtual K=96 bf16: {Ah,Al,Ah} x {Bh,Bh,Bl} ----
        #pragma unroll
        for (int s = 0; s < 6; s++) {
            const uint32_t aBase = sb + ((s < 2 || s >= 4) ? T_AH : T_AL);
            const uint32_t bBase = sb + ((s < 4) ? T_BH : T_BL);
            const int ks = (s & 1) * 16;

            uint32_t a[4][4];
            const int cA = (ks >> 3) + ((lane >> 4) & 1);
            #pragma unroll
            for (int mt = 0; mt < 4; mt++) {
                const int row = wm + mt * 16 + (lane & 15);
                ldsm_x4(aBase + row * 80 + cA * 16,
                        a[mt][0], a[mt][1], a[mt][2], a[mt][3]);
            }
            uint32_t b[4][2];
            const int cB = (ks >> 3) + ((lane >> 3) & 1);
            #pragma unroll
            for (int p = 0; p < 2; p++) {
                const int row = wn + p * 16 + ((lane >> 4) & 1) * 8 + (lane & 7);
                uint32_t r0, r1, r2, r3;
                ldsm_x4(bBase + row * 80 + cB * 16, r0, r1, r2, r3);
                b[p * 2][0] = r0; b[p * 2][1] = r1;
                b[p * 2 + 1][0] = r2; b[p * 2 + 1][1] = r3;
            }
            #pragma unroll
            for (int mt = 0; mt < 4; mt++)
                #pragma unroll
                for (int nt = 0; nt < 4; nt++)
                    mma16816(acc[mt][nt], a[mt], b[nt]);
        }
        __syncthreads();
    }

    // ---- epilogue ----
    #pragma unroll
    for (int mt = 0; mt < 4; mt++) {
        #pragma unroll
        for (int nt = 0; nt < 4; nt++) {
            const int col = n0 + wn + nt * 8 + (lane & 3) * 2;
            const int row0 = m0 + wm + mt * 16 + (lane >> 2);
            float2 bb = *(const float2*)(bias + col);
            if (MODE == 0) {
                float2 o0, o1;
                o0.x = acc[mt][nt][0] + bb.x;
                o0.y = acc[mt][nt][1] + bb.y;
                o1.x = acc[mt][nt][2] + bb.x;
                o1.y = acc[mt][nt][3] + bb.y;
                *(float2*)(C + (size_t)row0 * ldc + col) = o0;
                *(float2*)(C + (size_t)(row0 + 8) * ldc + col) = o1;
            } else {
                float2 sc = *(const float2*)(scale + col);
                float2 sh = *(const float2*)(shift + col);
                float2 v0 = *(const float2*)(oc + (size_t)row0 * ldc + col);
                float2 v1 = *(const float2*)(oc + (size_t)(row0 + 8) * ldc + col);
                float2 o0, o1;
                o0.x = fmaxf(acc[mt][nt][0] + bb.x, 0.f) * fmaxf(fmaf(v0.x, sc.x, sh.x), 0.f);
                o0.y = fmaxf(acc[mt][nt][1] + bb.y, 0.f) * fmaxf(fmaf(v0.y, sc.y, sh.y), 0.f);
                o1.x = fmaxf(acc[mt][nt][2] + bb.x, 0.f) * fmaxf(fmaf(v1.x, sc.x, sh.x), 0.f);
                o1.y = fmaxf(acc[mt][nt][3] + bb.y, 0.f) * fmaxf(fmaf(v1.y, sc.y, sh.y), 0.f);
                *(float2*)(C + (size_t)row0 * ldc + col) = o0;
                *(float2*)(C + (size_t)(row0 + 8) * ldc + col) = o1;
            }
        }
    }
}

// ---------------- K2: per-node attention ----------------
__global__ __launch_bounds__(256) void attn_kernel(
    const float* __restrict__ x, const float* __restrict__ nb)
{
    __shared__ __align__(16) float Xs[KNB * DIN];
    __shared__ float tsm[DIN];
    __shared__ float es[KNB], sx[KNB], att[KNB];
    __shared__ float red[8];
    __shared__ float s_eb;

    const int n = blockIdx.x;
    const int t = threadIdx.x;
    const int w = t >> 5, l = t & 31;

    const float4* nb4 = (const float4*)(nb + (size_t)n * KNB * DIN);
    float4* Xs4 = (float4*)Xs;
    #pragma unroll
    for (int j = 0; j < 8; j++) Xs4[t + j * 256] = nb4[t + j * 256];
    tsm[t] = d_ts[(size_t)n * DIN + t];

    float eb = x[(size_t)n * DIN + t] * d_v[t];
    #pragma unroll
    for (int off = 16; off > 0; off >>= 1) eb += __shfl_down_sync(0xffffffffu, eb, off);
    if (l == 0) red[w] = eb;
    __syncthreads();
    if (t == 0) {
        float s = 0.f;
        #pragma unroll
        for (int ww = 0; ww < 8; ww++) s += red[ww];
        s_eb = s + d_c0[0];
    }

    #pragma unroll
    for (int rr = 0; rr < 4; rr++) {
        int k = w * 4 + rr;
        const float* xr = &Xs[k * DIN];
        float e = 0.f, s = 0.f;
        #pragma unroll
        for (int j = 0; j < 8; j++) {
            float vx = xr[l + 32 * j];
            e = fmaf(vx, tsm[l + 32 * j], e);
            s += vx;
        }
        #pragma unroll
        for (int off = 16; off > 0; off >>= 1) {
            e += __shfl_down_sync(0xffffffffu, e, off);
            s += __shfl_down_sync(0xffffffffu, s, off);
        }
        if (l == 0) { es[k] = e; sx[k] = s; }
    }
    __syncthreads();

    if (t < 32) {
        float e = (sx[t] == 0.0f) ? 1e-12f : (es[t] + s_eb);
        float m = e;
        #pragma unroll
        for (int off = 16; off > 0; off >>= 1) m = fmaxf(m, __shfl_xor_sync(0xffffffffu, m, off));
        float p = __expf(e - m);
        float s = p;
        #pragma unroll
        for (int off = 16; off > 0; off >>= 1) s += __shfl_xor_sync(0xffffffffu, s, off);
        att[t] = p / s;
    }
    __syncthreads();

    float accv = 0.f;
    #pragma unroll
    for (int k = 0; k < KNB; k++) accv = fmaf(att[k], Xs[k * DIN + t], accv);
    d_c[(size_t)n * DIN + t] = accv;
}

// ---------------- BN: deterministic two-pass ----------------
__global__ void bn_reduce_kernel()
{
    const int t = threadIdx.x;
    const int b = blockIdx.x;
    float s0 = 0.f, q0 = 0.f, s1 = 0.f, q1 = 0.f;
    for (int r = 0; r < 128; r++) {
        size_t row = (size_t)(b * 128 + r);
        float v0 = d_outcat[row * DCAT + t];
        float v1 = d_outcat[row * DCAT + t + 256];
        s0 += v0; q0 = fmaf(v0, v0, q0);
        s1 += v1; q1 = fmaf(v1, v1, q1);
    }
    d_part[b * 1024 + t]       = s0;
    d_part[b * 1024 + t + 256] = s1;
    d_part[b * 1024 + 512 + t]       = q0;
    d_part[b * 1024 + 512 + t + 256] = q1;
}

__global__ void bn_finalize_kernel(const float* __restrict__ gamma,
                                   const float* __restrict__ beta)
{
    const int c = blockIdx.x * 256 + threadIdx.x;
    float s = 0.f, q = 0.f;
    for (int p = 0; p < 128; p++) {
        s += d_part[p * 1024 + c];
        q += d_part[p * 1024 + 512 + c];
    }
    const float invN = 1.0f / (float)N_NODES;
    float mean = s * invN;
    float var  = q * invN - mean * mean;
    float inv  = rsqrtf(var + EPSBN);
    float scl  = gamma[c] * inv;
    d_scale[c] = scl;
    d_shift[c] = beta[c] - mean * scl;
}

// ---------------- launch ----------------
extern "C" void kernel_launch(void* const* d_in, const int* in_sizes, int n_in,
                              void* d_out, int out_size)
{
    const float* x    = (const float*)d_in[0];
    const float* nb   = (const float*)d_in[1];
    const float* Wq   = (const float*)d_in[2];
    const float* bq   = (const float*)d_in[3];
    const float* Wk   = (const float*)d_in[4];
    const float* bk   = (const float*)d_in[5];
    const float* Wv   = (const float*)d_in[6];
    const float* bv   = (const float*)d_in[7];
    const float* Wno  = (const float*)d_in[8];
    const float* bno  = (const float*)d_in[9];
    const float* Wio  = (const float*)d_in[10];
    const float* bio  = (const float*)d_in[11];
    const float* Wg   = (const float*)d_in[12];
    const float* bg   = (const float*)d_in[13];
    const float* gamma= (const float*)d_in[14];
    const float* beta = (const float*)d_in[15];
    float* out = (float*)d_out;

    float *pM, *ptb, *pW2, *pb2, *pts, *pc, *poc, *pscale, *pshift;
    cudaGetSymbolAddress((void**)&pM,  d_M);
    cudaGetSymbolAddress((void**)&ptb, d_tb);
    cudaGetSymbolAddress((void**)&pW2, d_W2);
    cudaGetSymbolAddress((void**)&pb2, d_b2);
    cudaGetSymbolAddress((void**)&pts, d_ts);
    cudaGetSymbolAddress((void**)&pc,  d_c);
    cudaGetSymbolAddress((void**)&poc, d_outcat);
    cudaGetSymbolAddress((void**)&pscale, d_scale);
    cudaGetSymbolAddress((void**)&pshift, d_shift);

    precompute_kernel<<<dim3(256, 3), 256>>>(Wq, bq, Wk, bk, Wv, bv, Wno, bno);

    // G1: ts = x @ M^T + tb
    tc_gemm<0><<<dim3(2, 128), 256, SMEM_GEMM>>>(x, DIN, pM, DIN, ptb, pts, DIN, DIN,
                                                 nullptr, nullptr, nullptr);
    // G2: self_out = x @ Wio^T + bio -> outcat[:, 0:256]
    tc_gemm<0><<<dim3(2, 128), 256, SMEM_GEMM>>>(x, DIN, Wio, DIN, bio, poc, DCAT, DIN,
                                                 nullptr, nullptr, nullptr);
    // attention -> c
    attn_kernel<<<N_NODES, 256>>>(x, nb);

    // G3: neigh_out = c @ W2^T + b2 -> outcat[:, 256:512]
    tc_gemm<0><<<dim3(2, 128), 256, SMEM_GEMM>>>(pc, DIN, pW2, DOUT, pb2, poc + DOUT, DCAT, DOUT,
                                                 nullptr, nullptr, nullptr);

    bn_reduce_kernel<<<128, 256>>>();
    bn_finalize_kernel<<<2, 256>>>(gamma, beta);

    // G4: gate GEMM + fused BN/gate epilogue -> d_out
    tc_gemm<1><<<dim3(4, 128), 256, SMEM_GEMM>>>(poc, DCAT, Wg, DCAT, bg, out, DCAT, DCAT,
                                                 poc, pscale, pshift);
}

// round 6
// speedup vs baseline: 1.6561x; 1.0607x over previous
#include <cuda_runtime.h>
#include <cuda_bf16.h>
#include <cstdint>

#define N_NODES 16384
#define KNB 32
#define DIN 256
#define DOUT 256
#define DCAT 512
#define EPSBN 1e-5f

// ---------------- scratch (static __device__, no allocs) ----------------
__device__ float d_M[DIN * DIN];
__device__ float d_W2[DOUT * DOUT];
__device__ float d_bias12[DCAT];            // [tb | bio]
__device__ float d_b2[DOUT];
__device__ float d_v[DIN];
__device__ float d_c0[1];
__device__ float d_ts[N_NODES * DIN];
__device__ float d_outcat[N_NODES * DCAT];
__device__ float d_part[128 * 1024];
__device__ float d_scale[DCAT];
__device__ float d_shift[DCAT];
// pre-split bf16 operands
__device__ __nv_bfloat16 d_B12h[DCAT * DIN], d_B12l[DCAT * DIN];   // [M;Wio]
__device__ __nv_bfloat16 d_B3h[DOUT * DIN],  d_B3l[DOUT * DIN];    // W2
__device__ __nv_bfloat16 d_B4h[DCAT * DCAT], d_B4l[DCAT * DCAT];   // Wg
__device__ __nv_bfloat16 d_ch[N_NODES * DIN],  d_cl[N_NODES * DIN];
__device__ __nv_bfloat16 d_och[N_NODES * DCAT], d_ocl[N_NODES * DCAT];

// ---------------- helpers ----------------
__device__ __forceinline__ uint32_t smem_u32(const void* p) {
    uint32_t a;
    asm("{ .reg .u64 t; cvta.to.shared.u64 t, %1; cvt.u32.u64 %0, t; }" : "=r"(a) : "l"(p));
    return a;
}
__device__ __forceinline__ void ldsm_x4(uint32_t addr, uint32_t& r0, uint32_t& r1,
                                        uint32_t& r2, uint32_t& r3) {
    asm volatile("ldmatrix.sync.aligned.m8n8.x4.shared.b16 {%0,%1,%2,%3}, [%4];"
                 : "=r"(r0), "=r"(r1), "=r"(r2), "=r"(r3) : "r"(addr));
}
__device__ __forceinline__ void mma16816(float* c, const uint32_t* a, const uint32_t* b) {
    asm volatile(
        "mma.sync.aligned.m16n8k16.row.col.f32.bf16.bf16.f32 "
        "{%0,%1,%2,%3}, {%4,%5,%6,%7}, {%8,%9}, {%0,%1,%2,%3};"
        : "+f"(c[0]), "+f"(c[1]), "+f"(c[2]), "+f"(c[3])
        : "r"(a[0]), "r"(a[1]), "r"(a[2]), "r"(a[3]), "r"(b[0]), "r"(b[1]));
}
__device__ __forceinline__ void cpa16(uint32_t saddr, const void* g) {
    asm volatile("cp.async.cg.shared.global [%0], [%1], 16;" :: "r"(saddr), "l"(g));
}
__device__ __forceinline__ void cpa_commit() {
    asm volatile("cp.async.commit_group;" ::: "memory");
}
template <int NP>
__device__ __forceinline__ void cpa_wait() {
    asm volatile("cp.async.wait_group %0;" :: "n"(NP) : "memory");
}
__device__ __forceinline__ uint32_t pack_bf16(__nv_bfloat16 lo, __nv_bfloat16 hi) {
    return ((uint32_t)__bfloat16_as_ushort(hi) << 16) | (uint32_t)__bfloat16_as_ushort(lo);
}
__device__ __forceinline__ void split4(float4 v, uint2& hi, uint2& lo) {
    __nv_bfloat16 hx = __float2bfloat16(v.x);
    __nv_bfloat16 hy = __float2bfloat16(v.y);
    __nv_bfloat16 hz = __float2bfloat16(v.z);
    __nv_bfloat16 hw = __float2bfloat16(v.w);
    __nv_bfloat16 lx = __float2bfloat16(v.x - __bfloat162float(hx));
    __nv_bfloat16 ly = __float2bfloat16(v.y - __bfloat162float(hy));
    __nv_bfloat16 lz = __float2bfloat16(v.z - __bfloat162float(hz));
    __nv_bfloat16 lw = __float2bfloat16(v.w - __bfloat162float(hw));
    hi.x = pack_bf16(hx, hy); hi.y = pack_bf16(hz, hw);
    lo.x = pack_bf16(lx, ly); lo.y = pack_bf16(lz, lw);
}
// write fp32 pair + bf16 hi/lo pair into outcat buffers
__device__ __forceinline__ void outstore(int row, int cc, float a, float b) {
    const size_t idx = (size_t)row * DCAT + cc;
    *(float2*)&d_outcat[idx] = make_float2(a, b);
    __nv_bfloat16 ha = __float2bfloat16(a), hb = __float2bfloat16(b);
    __nv_bfloat16 la = __float2bfloat16(a - __bfloat162float(ha));
    __nv_bfloat16 lb = __float2bfloat16(b - __bfloat162float(hb));
    *(uint32_t*)&d_och[idx] = pack_bf16(ha, hb);
    *(uint32_t*)&d_ocl[idx] = pack_bf16(la, lb);
}

// ---------------- K0: weight composition ----------------
__global__ void precompute_kernel(
    const float* __restrict__ Wq, const float* __restrict__ bq,
    const float* __restrict__ Wk, const float* __restrict__ bk,
    const float* __restrict__ Wv, const float* __restrict__ bv,
    const float* __restrict__ Wno, const float* __restrict__ bno,
    const float* __restrict__ bio)
{
    const int t = threadIdx.x;
    const int j = blockIdx.x;
    if (blockIdx.y == 0) {
        float acc = 0.f;
        #pragma unroll 4
        for (int o = 0; o < DOUT; o++) acc = fmaf(Wk[o * DIN + j], Wq[o * DIN + t], acc);
        d_M[j * DIN + t] = acc;
    } else if (blockIdx.y == 1) {
        float acc = 0.f;
        #pragma unroll 4
        for (int d = 0; d < DOUT; d++) acc = fmaf(Wno[j * DOUT + d], Wv[d * DIN + t], acc);
        d_W2[j * DOUT + t] = acc;
    } else if (blockIdx.x == 0) {
        float tb = 0.f, vv = 0.f, b2 = 0.f;
        for (int o = 0; o < DOUT; o++) {
            tb = fmaf(Wk[o * DIN + t], bq[o], tb);
            vv = fmaf(bk[o], Wq[o * DIN + t], vv);
        }
        for (int d = 0; d < DOUT; d++) b2 = fmaf(Wno[t * DOUT + d], bv[d], b2);
        d_bias12[t]       = tb;
        d_bias12[t + 256] = bio[t];
        d_v[t]  = vv;
        d_b2[t] = b2 + bno[t];
        if (t == 0) {
            float c = 0.f;
            for (int o = 0; o < DOUT; o++) c = fmaf(bk[o], bq[o], c);
            d_c0[0] = c;
        }
    }
}

// ---------------- K0b: split weights to bf16 hi/lo ----------------
__global__ void split_weights_kernel(const float* __restrict__ Wio,
                                     const float* __restrict__ Wg)
{
    const int t = threadIdx.x;
    const int row = blockIdx.x;
    if (blockIdx.y == 0) {
        // B12 = [M (rows 0..255) ; Wio (rows 256..511)], K=256
        float v = (row < 256) ? d_M[row * DIN + t] : Wio[(row - 256) * DIN + t];
        __nv_bfloat16 h = __float2bfloat16(v);
        d_B12h[row * DIN + t] = h;
        d_B12l[row * DIN + t] = __float2bfloat16(v - __bfloat162float(h));
    } else if (blockIdx.y == 1) {
        if (row < 256) {
            float v = d_W2[row * DIN + t];
            __nv_bfloat16 h = __float2bfloat16(v);
            d_B3h[row * DIN + t] = h;
            d_B3l[row * DIN + t] = __float2bfloat16(v - __bfloat162float(h));
        }
    } else {
        #pragma unroll
        for (int c = t; c < DCAT; c += 256) {
            float v = Wg[row * DCAT + c];
            __nv_bfloat16 h = __float2bfloat16(v);
            d_B4h[row * DCAT + c] = h;
            d_B4l[row * DCAT + c] = __float2bfloat16(v - __bfloat162float(h));
        }
    }
}

// ============ bf16-split tensor-core GEMM ============
// ASRC 0: A fp32, split in-kernel (single-buffered A tiles).
// ASRC 1: A pre-split bf16 hi/lo, cp.async double-buffered.
// B always pre-split bf16, cp.async double-buffered.
// MODE 0: G12 dual target (col<256 -> d_ts ; else outcat[:,0:256] + hi/lo)
// MODE 1: G3 -> outcat[:,256:512] + hi/lo
// MODE 2: G4 gate epilogue -> Cout
// smem layout:
//   ASRC1: buf*40960 + {AH 0, AL 10240, BH 20480, BL 30720}   total 81920
//   ASRC0: {AH 0, AL 10240}, B: 20480 + buf*20480 + {H 0, L 10240}  total 61440
template <int ASRC, int MODE>
__global__ __launch_bounds__(256, 2) void tc_gemm(
    const float* __restrict__ Afp,
    const __nv_bfloat16* __restrict__ Abh, const __nv_bfloat16* __restrict__ Abl,
    int lda,
    const __nv_bfloat16* __restrict__ Bh, const __nv_bfloat16* __restrict__ Bl,
    const float* __restrict__ bias, float* __restrict__ Cout, int Kdim)
{
    extern __shared__ char smem[];
    const uint32_t sb = smem_u32(smem);
    const int tid = threadIdx.x;
    const int wid = tid >> 5, lane = tid & 31;
    const int m0 = blockIdx.y * 128;
    const int n0 = blockIdx.x * 128;
    const int wm = (wid & 1) * 64;
    const int wn = (wid >> 1) * 32;

    float acc[4][4][4];
    #pragma unroll
    for (int i = 0; i < 4; i++)
        #pragma unroll
        for (int j = 0; j < 4; j++)
            #pragma unroll
            for (int q = 0; q < 4; q++) acc[i][j][q] = 0.f;

    const int r  = tid >> 1;          // 0..127
    const int h2 = tid & 1;

    auto issueB = [&](int kc, int buf) {
        const __nv_bfloat16* gh = Bh + (size_t)(n0 + r) * Kdim + kc + h2 * 16;
        const __nv_bfloat16* gl = Bl + (size_t)(n0 + r) * Kdim + kc + h2 * 16;
        const uint32_t d = sb + (ASRC ? (uint32_t)(buf * 40960 + 20480)
                                      : (uint32_t)(20480 + buf * 20480))
                              + r * 80 + h2 * 32;
        cpa16(d, gh);          cpa16(d + 16, gh + 8);
        cpa16(d + 10240, gl);  cpa16(d + 10240 + 16, gl + 8);
    };
    auto issueA = [&](int kc, int buf) {   // ASRC==1 only
        const __nv_bfloat16* gh = Abh + (size_t)(m0 + r) * lda + kc + h2 * 16;
        const __nv_bfloat16* gl = Abl + (size_t)(m0 + r) * lda + kc + h2 * 16;
        const uint32_t d = sb + (uint32_t)(buf * 40960) + r * 80 + h2 * 32;
        cpa16(d, gh);          cpa16(d + 16, gh + 8);
        cpa16(d + 10240, gl);  cpa16(d + 10240 + 16, gl + 8);
    };
    auto loadSplitA = [&](int kc) {        // ASRC==0 only, single A buffer
        const int kh = h2 * 16;
        const float4* gp = (const float4*)(Afp + (size_t)(m0 + r) * lda + kc + kh);
        char* rowH = smem + r * 80;
        char* rowL = smem + 10240 + r * 80;
        #pragma unroll
        for (int q = 0; q < 4; q++) {
            uint2 h, l;
            split4(gp[q], h, l);
            const int kk = kh + q * 4;
            *(uint2*)(rowH + kk * 2) = h;
            *(uint2*)(rowL + kk * 2) = l;
        }
    };

    const int NC = Kdim >> 5;
    if (ASRC) issueA(0, 0);
    issueB(0, 0);
    cpa_commit();

    for (int ic = 0; ic < NC; ic++) {
        const int buf = ic & 1;
        if (ic + 1 < NC) {
            if (ASRC) issueA((ic + 1) << 5, buf ^ 1);
            issueB((ic + 1) << 5, buf ^ 1);
        }
        cpa_commit();
        if (!ASRC) loadSplitA(ic << 5);
        cpa_wait<1>();
        __syncthreads();

        const uint32_t aH = sb + (ASRC ? (uint32_t)(buf * 40960) : 0u);
        const uint32_t aL = aH + 10240;
        const uint32_t bH = sb + (ASRC ? (uint32_t)(buf * 40960 + 20480)
                                       : (uint32_t)(20480 + buf * 20480));
        const uint32_t bL = bH + 10240;

        #pragma unroll
        for (int s = 0; s < 6; s++) {
            const uint32_t aBase = (s < 2 || s >= 4) ? aH : aL;
            const uint32_t bBase = (s < 4) ? bH : bL;
            const int ks = (s & 1) * 16;

            uint32_t a[4][4];
            const int cA = (ks >> 3) + ((lane >> 4) & 1);
            #pragma unroll
            for (int mt = 0; mt < 4; mt++) {
                const int row = wm + mt * 16 + (lane & 15);
                ldsm_x4(aBase + row * 80 + cA * 16,
                        a[mt][0], a[mt][1], a[mt][2], a[mt][3]);
            }
            uint32_t b[4][2];
            const int cB = (ks >> 3) + ((lane >> 3) & 1);
            #pragma unroll
            for (int p = 0; p < 2; p++) {
                const int row = wn + p * 16 + ((lane >> 4) & 1) * 8 + (lane & 7);
                uint32_t r0, r1, r2, r3;
                ldsm_x4(bBase + row * 80 + cB * 16, r0, r1, r2, r3);
                b[p * 2][0] = r0; b[p * 2][1] = r1;
                b[p * 2 + 1][0] = r2; b[p * 2 + 1][1] = r3;
            }
            #pragma unroll
            for (int mt = 0; mt < 4; mt++)
                #pragma unroll
                for (int nt = 0; nt < 4; nt++)
                    mma16816(acc[mt][nt], a[mt], b[nt]);
        }
        __syncthreads();
    }

    // ---- epilogue ----
    #pragma unroll
    for (int mt = 0; mt < 4; mt++) {
        #pragma unroll
        for (int nt = 0; nt < 4; nt++) {
            const int col = n0 + wn + nt * 8 + (lane & 3) * 2;
            const int row0 = m0 + wm + mt * 16 + (lane >> 2);
            float2 bb = *(const float2*)(bias + col);
            const float v00 = acc[mt][nt][0] + bb.x;
            const float v01 = acc[mt][nt][1] + bb.y;
            const float v10 = acc[mt][nt][2] + bb.x;
            const float v11 = acc[mt][nt][3] + bb.y;
            if (MODE == 0) {
                if (col < 256) {
                    *(float2*)&d_ts[(size_t)row0 * DIN + col] = make_float2(v00, v01);
                    *(float2*)&d_ts[(size_t)(row0 + 8) * DIN + col] = make_float2(v10, v11);
                } else {
                    outstore(row0, col - 256, v00, v01);
                    outstore(row0 + 8, col - 256, v10, v11);
                }
            } else if (MODE == 1) {
                outstore(row0, col + 256, v00, v01);
                outstore(row0 + 8, col + 256, v10, v11);
            } else {
                float2 sc = *(const float2*)(d_scale + col);
                float2 sh = *(const float2*)(d_shift + col);
                float2 o0 = *(const float2*)&d_outcat[(size_t)row0 * DCAT + col];
                float2 o1 = *(const float2*)&d_outcat[(size_t)(row0 + 8) * DCAT + col];
                float2 w0, w1;
                w0.x = fmaxf(v00, 0.f) * fmaxf(fmaf(o0.x, sc.x, sh.x), 0.f);
                w0.y = fmaxf(v01, 0.f) * fmaxf(fmaf(o0.y, sc.y, sh.y), 0.f);
                w1.x = fmaxf(v10, 0.f) * fmaxf(fmaf(o1.x, sc.x, sh.x), 0.f);
                w1.y = fmaxf(v11, 0.f) * fmaxf(fmaf(o1.y, sc.y, sh.y), 0.f);
                *(float2*)(Cout + (size_t)row0 * DCAT + col) = w0;
                *(float2*)(Cout + (size_t)(row0 + 8) * DCAT + col) = w1;
            }
        }
    }
}

// ---------------- attention: register-row energies, one smem pass ----------------
__global__ __launch_bounds__(256) void attn_kernel(
    const float* __restrict__ x, const float* __restrict__ nb)
{
    __shared__ __align__(16) float Xs[KNB * DIN];   // 32 KB
    __shared__ float es[KNB], sx[KNB], att[KNB];
    __shared__ float red[8];

    const int n = blockIdx.x;
    const int t = threadIdx.x;
    const int w = t >> 5, l = t & 31;

    // each warp owns rows 4w..4w+3; lane l holds cols [4l..4l+3] and [128+4l..131+4l]
    float4 rowv[4][2];
    const float4* base = (const float4*)(nb + (size_t)n * KNB * DIN);
    #pragma unroll
    for (int rr = 0; rr < 4; rr++) {
        const int k = 4 * w + rr;
        rowv[rr][0] = base[k * 64 + l];
        rowv[rr][1] = base[k * 64 + 32 + l];
    }
    const float4* tsb = (const float4*)(d_ts + (size_t)n * DIN);
    const float4 ts0 = tsb[l], ts1 = tsb[32 + l];

    // ebias partial
    float eb = x[(size_t)n * DIN + t] * d_v[t];
    #pragma unroll
    for (int off = 16; off > 0; off >>= 1) eb += __shfl_down_sync(0xffffffffu, eb, off);
    if (l == 0) red[w] = eb;

    // energies + row sums from registers
    #pragma unroll
    for (int rr = 0; rr < 4; rr++) {
        const float4 a0 = rowv[rr][0], a1 = rowv[rr][1];
        float e = a0.x * ts0.x + a0.y * ts0.y + a0.z * ts0.z + a0.w * ts0.w
                + a1.x * ts1.x + a1.y * ts1.y + a1.z * ts1.z + a1.w * ts1.w;
        float s = a0.x + a0.y + a0.z + a0.w + a1.x + a1.y + a1.z + a1.w;
        #pragma unroll
        for (int off = 16; off > 0; off >>= 1) {
            e += __shfl_down_sync(0xffffffffu, e, off);
            s += __shfl_down_sync(0xffffffffu, s, off);
        }
        if (l == 0) { es[4 * w + rr] = e; sx[4 * w + rr] = s; }
    }

    // stash rows into smem for the weighted-sum pass
    #pragma unroll
    for (int rr = 0; rr < 4; rr++) {
        const int k = 4 * w + rr;
        float4* xr = (float4*)&Xs[k * DIN];
        xr[l] = rowv[rr][0];
        xr[32 + l] = rowv[rr][1];
    }
    __syncthreads();

    if (w == 0) {
        float v = (l < 8) ? red[l] : 0.f;
        #pragma unroll
        for (int off = 16; off > 0; off >>= 1) v += __shfl_xor_sync(0xffffffffu, v, off);
        const float s_eb = v + d_c0[0];
        float e = (sx[l] == 0.0f) ? 1e-12f : (es[l] + s_eb);
        float m = e;
        #pragma unroll
        for (int off = 16; off > 0; off >>= 1) m = fmaxf(m, __shfl_xor_sync(0xffffffffu, m, off));
        float p = __expf(e - m);
        float s = p;
        #pragma unroll
        for (int off = 16; off > 0; off >>= 1) s += __shfl_xor_sync(0xffffffffu, s, off);
        att[l] = p / s;
    }
    __syncthreads();

    float accv = 0.f;
    #pragma unroll
    for (int k = 0; k < KNB; k++) accv = fmaf(att[k], Xs[k * DIN + t], accv);

    // write c as bf16 hi/lo (consumed by G3 without any split)
    __nv_bfloat16 h = __float2bfloat16(accv);
    d_ch[(size_t)n * DIN + t] = h;
    d_cl[(size_t)n * DIN + t] = __float2bfloat16(accv - __bfloat162float(h));
}

// ---------------- BN: deterministic two-pass ----------------
__global__ void bn_reduce_kernel()
{
    const int t = threadIdx.x;
    const int b = blockIdx.x;
    float s0 = 0.f, q0 = 0.f, s1 = 0.f, q1 = 0.f;
    for (int r = 0; r < 128; r++) {
        size_t row = (size_t)(b * 128 + r);
        float v0 = d_outcat[row * DCAT + t];
        float v1 = d_outcat[row * DCAT + t + 256];
        s0 += v0; q0 = fmaf(v0, v0, q0);
        s1 += v1; q1 = fmaf(v1, v1, q1);
    }
    d_part[b * 1024 + t]       = s0;
    d_part[b * 1024 + t + 256] = s1;
    d_part[b * 1024 + 512 + t]       = q0;
    d_part[b * 1024 + 512 + t + 256] = q1;
}

__global__ void bn_finalize_kernel(const float* __restrict__ gamma,
                                   const float* __restrict__ beta)
{
    const int c = blockIdx.x * 256 + threadIdx.x;
    float s = 0.f, q = 0.f;
    for (int p = 0; p < 128; p++) {
        s += d_part[p * 1024 + c];
        q += d_part[p * 1024 + 512 + c];
    }
    const float invN = 1.0f / (float)N_NODES;
    float mean = s * invN;
    float var  = q * invN - mean * mean;
    float inv  = rsqrtf(var + EPSBN);
    float scl  = gamma[c] * inv;
    d_scale[c] = scl;
    d_shift[c] = beta[c] - mean * scl;
}

// ---------------- launch ----------------
extern "C" void kernel_launch(void* const* d_in, const int* in_sizes, int n_in,
                              void* d_out, int out_size)
{
    const float* x    = (const float*)d_in[0];
    const float* nb   = (const float*)d_in[1];
    const float* Wq   = (const float*)d_in[2];
    const float* bq   = (const float*)d_in[3];
    const float* Wk   = (const float*)d_in[4];
    const float* bk   = (const float*)d_in[5];
    const float* Wv   = (const float*)d_in[6];
    const float* bv   = (const float*)d_in[7];
    const float* Wno  = (const float*)d_in[8];
    const float* bno  = (const float*)d_in[9];
    const float* Wio  = (const float*)d_in[10];
    const float* bio  = (const float*)d_in[11];
    const float* Wg   = (const float*)d_in[12];
    const float* bg   = (const float*)d_in[13];
    const float* gamma= (const float*)d_in[14];
    const float* beta = (const float*)d_in[15];
    float* out = (float*)d_out;

    void *pB12h, *pB12l, *pB3h, *pB3l, *pB4h, *pB4l;
    void *pch, *pcl, *poch, *pocl, *pbias12, *pb2;
    cudaGetSymbolAddress(&pB12h, d_B12h);
    cudaGetSymbolAddress(&pB12l, d_B12l);
    cudaGetSymbolAddress(&pB3h,  d_B3h);
    cudaGetSymbolAddress(&pB3l,  d_B3l);
    cudaGetSymbolAddress(&pB4h,  d_B4h);
    cudaGetSymbolAddress(&pB4l,  d_B4l);
    cudaGetSymbolAddress(&pch,   d_ch);
    cudaGetSymbolAddress(&pcl,   d_cl);
    cudaGetSymbolAddress(&poch,  d_och);
    cudaGetSymbolAddress(&pocl,  d_ocl);
    cudaGetSymbolAddress(&pbias12, d_bias12);
    cudaGetSymbolAddress(&pb2,     d_b2);

    static bool attr_done = false;
    if (!attr_done) {
        cudaFuncSetAttribute(tc_gemm<0, 0>, cudaFuncAttributeMaxDynamicSharedMemorySize, 61440);
        cudaFuncSetAttribute(tc_gemm<1, 1>, cudaFuncAttributeMaxDynamicSharedMemorySize, 81920);
        cudaFuncSetAttribute(tc_gemm<1, 2>, cudaFuncAttributeMaxDynamicSharedMemorySize, 81920);
        attr_done = true;
    }

    // weight composition + vectors
    precompute_kernel<<<dim3(256, 3), 256>>>(Wq, bq, Wk, bk, Wv, bv, Wno, bno, bio);
    // split all B operands to bf16 hi/lo
    split_weights_kernel<<<dim3(512, 3), 256>>>(Wio, Wg);

    // G12: [ts | self_out] = x @ [M;Wio]^T + [tb|bio]
    tc_gemm<0, 0><<<dim3(4, 128), 256, 61440>>>(
        x, nullptr, nullptr, DIN,
        (const __nv_bfloat16*)pB12h, (const __nv_bfloat16*)pB12l,
        (const float*)pbias12, nullptr, DIN);

    // attention -> c (bf16 hi/lo)
    attn_kernel<<<N_NODES, 256>>>(x, nb);

    // G3: neigh_out = c @ W2^T + b2 -> outcat[:,256:512]
    tc_gemm<1, 1><<<dim3(2, 128), 256, 81920>>>(
        nullptr, (const __nv_bfloat16*)pch, (const __nv_bfloat16*)pcl, DIN,
        (const __nv_bfloat16*)pB3h, (const __nv_bfloat16*)pB3l,
        (const float*)pb2, nullptr, DIN);

    bn_reduce_kernel<<<128, 256>>>();
    bn_finalize_kernel<<<2, 256>>>(gamma, beta);

    // G4: gate GEMM + fused BN/gate epilogue -> d_out
    tc_gemm<1, 2><<<dim3(4, 128), 256, 81920>>>(
        nullptr, (const __nv_bfloat16*)poch, (const __nv_bfloat16*)pocl, DCAT,
        (const __nv_bfloat16*)pB4h, (const __nv_bfloat16*)pB4l,
        bg, out, DCAT);
}

// round 10
// speedup vs baseline: 1.7455x; 1.0539x over previous
#include <cuda_runtime.h>
#include <cuda_bf16.h>
#include <cstdint>

#define N_NODES 16384
#define KNB 32
#define DIN 256
#define DOUT 256
#define DCAT 512
#define EPSBN 1e-5f

// ---------------- scratch (static __device__, no allocs) ----------------
__device__ float d_M[DIN * DIN];
__device__ float d_W2[DOUT * DOUT];
__device__ float d_bias12[DCAT];            // [tb | bio]
__device__ float d_b2[DOUT];
__device__ float d_v[DIN];
__device__ float d_c0[1];
__device__ float d_ts[N_NODES * DIN];
__device__ float d_outcat[N_NODES * DCAT];
__device__ float d_part[128 * 1024];
__device__ float d_scale[DCAT];
__device__ float d_shift[DCAT];
// pre-split bf16 operands
__device__ __nv_bfloat16 d_B12h[DCAT * DIN], d_B12l[DCAT * DIN];   // [M;Wio]
__device__ __nv_bfloat16 d_B3h[DOUT * DIN],  d_B3l[DOUT * DIN];    // W2
__device__ __nv_bfloat16 d_B4h[DCAT * DCAT], d_B4l[DCAT * DCAT];   // Wg
__device__ __nv_bfloat16 d_ch[N_NODES * DIN],  d_cl[N_NODES * DIN];
__device__ __nv_bfloat16 d_och[N_NODES * DCAT], d_ocl[N_NODES * DCAT];

// ---------------- helpers ----------------
__device__ __forceinline__ uint32_t smem_u32(const void* p) {
    uint32_t a;
    asm("{ .reg .u64 t; cvta.to.shared.u64 t, %1; cvt.u32.u64 %0, t; }" : "=r"(a) : "l"(p));
    return a;
}
__device__ __forceinline__ void ldsm_x4(uint32_t addr, uint32_t& r0, uint32_t& r1,
                                        uint32_t& r2, uint32_t& r3) {
    asm volatile("ldmatrix.sync.aligned.m8n8.x4.shared.b16 {%0,%1,%2,%3}, [%4];"
                 : "=r"(r0), "=r"(r1), "=r"(r2), "=r"(r3) : "r"(addr));
}
__device__ __forceinline__ void mma16816(float* c, const uint32_t* a, const uint32_t* b) {
    asm volatile(
        "mma.sync.aligned.m16n8k16.row.col.f32.bf16.bf16.f32 "
        "{%0,%1,%2,%3}, {%4,%5,%6,%7}, {%8,%9}, {%0,%1,%2,%3};"
        : "+f"(c[0]), "+f"(c[1]), "+f"(c[2]), "+f"(c[3])
        : "r"(a[0]), "r"(a[1]), "r"(a[2]), "r"(a[3]), "r"(b[0]), "r"(b[1]));
}
__device__ __forceinline__ void cpa16(uint32_t saddr, const void* g) {
    asm volatile("cp.async.cg.shared.global [%0], [%1], 16;" :: "r"(saddr), "l"(g));
}
__device__ __forceinline__ void cpa_commit() {
    asm volatile("cp.async.commit_group;" ::: "memory");
}
template <int NP>
__device__ __forceinline__ void cpa_wait() {
    asm volatile("cp.async.wait_group %0;" :: "n"(NP) : "memory");
}
__device__ __forceinline__ uint32_t pack_bf16(__nv_bfloat16 lo, __nv_bfloat16 hi) {
    return ((uint32_t)__bfloat16_as_ushort(hi) << 16) | (uint32_t)__bfloat16_as_ushort(lo);
}
__device__ __forceinline__ void split4(float4 v, uint2& hi, uint2& lo) {
    __nv_bfloat16 hx = __float2bfloat16(v.x);
    __nv_bfloat16 hy = __float2bfloat16(v.y);
    __nv_bfloat16 hz = __float2bfloat16(v.z);
    __nv_bfloat16 hw = __float2bfloat16(v.w);
    __nv_bfloat16 lx = __float2bfloat16(v.x - __bfloat162float(hx));
    __nv_bfloat16 ly = __float2bfloat16(v.y - __bfloat162float(hy));
    __nv_bfloat16 lz = __float2bfloat16(v.z - __bfloat162float(hz));
    __nv_bfloat16 lw = __float2bfloat16(v.w - __bfloat162float(hw));
    hi.x = pack_bf16(hx, hy); hi.y = pack_bf16(hz, hw);
    lo.x = pack_bf16(lx, ly); lo.y = pack_bf16(lz, lw);
}
__device__ __forceinline__ void outstore(int row, int cc, float a, float b) {
    const size_t idx = (size_t)row * DCAT + cc;
    *(float2*)&d_outcat[idx] = make_float2(a, b);
    __nv_bfloat16 ha = __float2bfloat16(a), hb = __float2bfloat16(b);
    __nv_bfloat16 la = __float2bfloat16(a - __bfloat162float(ha));
    __nv_bfloat16 lb = __float2bfloat16(b - __bfloat162float(hb));
    *(uint32_t*)&d_och[idx] = pack_bf16(ha, hb);
    *(uint32_t*)&d_ocl[idx] = pack_bf16(la, lb);
}

// ---------------- K0: weight composition ----------------
__global__ void precompute_kernel(
    const float* __restrict__ Wq, const float* __restrict__ bq,
    const float* __restrict__ Wk, const float* __restrict__ bk,
    const float* __restrict__ Wv, const float* __restrict__ bv,
    const float* __restrict__ Wno, const float* __restrict__ bno,
    const float* __restrict__ bio)
{
    const int t = threadIdx.x;
    const int j = blockIdx.x;
    if (blockIdx.y == 0) {
        float acc = 0.f;
        #pragma unroll 4
        for (int o = 0; o < DOUT; o++) acc = fmaf(Wk[o * DIN + j], Wq[o * DIN + t], acc);
        d_M[j * DIN + t] = acc;
    } else if (blockIdx.y == 1) {
        float acc = 0.f;
        #pragma unroll 4
        for (int d = 0; d < DOUT; d++) acc = fmaf(Wno[j * DOUT + d], Wv[d * DIN + t], acc);
        d_W2[j * DOUT + t] = acc;
    } else if (blockIdx.x == 0) {
        float tb = 0.f, vv = 0.f, b2 = 0.f;
        for (int o = 0; o < DOUT; o++) {
            tb = fmaf(Wk[o * DIN + t], bq[o], tb);
            vv = fmaf(bk[o], Wq[o * DIN + t], vv);
        }
        for (int d = 0; d < DOUT; d++) b2 = fmaf(Wno[t * DOUT + d], bv[d], b2);
        d_bias12[t]       = tb;
        d_bias12[t + 256] = bio[t];
        d_v[t]  = vv;
        d_b2[t] = b2 + bno[t];
        if (t == 0) {
            float c = 0.f;
            for (int o = 0; o < DOUT; o++) c = fmaf(bk[o], bq[o], c);
            d_c0[0] = c;
        }
    }
}

// ---------------- K0b: split weights to bf16 hi/lo ----------------
__global__ void split_weights_kernel(const float* __restrict__ Wio,
                                     const float* __restrict__ Wg)
{
    const int t = threadIdx.x;
    const int row = blockIdx.x;
    if (blockIdx.y == 0) {
        float v = (row < 256) ? d_M[row * DIN + t] : Wio[(row - 256) * DIN + t];
        __nv_bfloat16 h = __float2bfloat16(v);
        d_B12h[row * DIN + t] = h;
        d_B12l[row * DIN + t] = __float2bfloat16(v - __bfloat162float(h));
    } else if (blockIdx.y == 1) {
        if (row < 256) {
            float v = d_W2[row * DIN + t];
            __nv_bfloat16 h = __float2bfloat16(v);
            d_B3h[row * DIN + t] = h;
            d_B3l[row * DIN + t] = __float2bfloat16(v - __bfloat162float(h));
        }
    } else {
        #pragma unroll
        for (int c = t; c < DCAT; c += 256) {
            float v = Wg[row * DCAT + c];
            __nv_bfloat16 h = __float2bfloat16(v);
            d_B4h[row * DCAT + c] = h;
            d_B4l[row * DCAT + c] = __float2bfloat16(v - __bfloat162float(h));
        }
    }
}

// ============ bf16-split tensor-core GEMM ============
// ASRC 0: A fp32, split in-kernel. ASRC 1: A pre-split bf16 hi/lo (cp.async dbuf).
// MODE 0: G12 dual target; MODE 1: G3 -> outcat[:,256:512]; MODE 2: G4 gate -> Cout
template <int ASRC, int MODE>
__global__ __launch_bounds__(256, 2) void tc_gemm(
    const float* __restrict__ Afp,
    const __nv_bfloat16* __restrict__ Abh, const __nv_bfloat16* __restrict__ Abl,
    int lda,
    const __nv_bfloat16* __restrict__ Bh, const __nv_bfloat16* __restrict__ Bl,
    const float* __restrict__ bias, float* __restrict__ Cout, int Kdim)
{
    extern __shared__ char smem[];
    const uint32_t sb = smem_u32(smem);
    const int tid = threadIdx.x;
    const int wid = tid >> 5, lane = tid & 31;
    const int m0 = blockIdx.y * 128;
    const int n0 = blockIdx.x * 128;
    const int wm = (wid & 1) * 64;
    const int wn = (wid >> 1) * 32;

    float acc[4][4][4];
    #pragma unroll
    for (int i = 0; i < 4; i++)
        #pragma unroll
        for (int j = 0; j < 4; j++)
            #pragma unroll
            for (int q = 0; q < 4; q++) acc[i][j][q] = 0.f;

    const int r  = tid >> 1;          // 0..127
    const int h2 = tid & 1;

    auto issueB = [&](int kc, int buf) {
        const __nv_bfloat16* gh = Bh + (size_t)(n0 + r) * Kdim + kc + h2 * 16;
        const __nv_bfloat16* gl = Bl + (size_t)(n0 + r) * Kdim + kc + h2 * 16;
        const uint32_t d = sb + (ASRC ? (uint32_t)(buf * 40960 + 20480)
                                      : (uint32_t)(20480 + buf * 20480))
                              + r * 80 + h2 * 32;
        cpa16(d, gh);          cpa16(d + 16, gh + 8);
        cpa16(d + 10240, gl);  cpa16(d + 10240 + 16, gl + 8);
    };
    auto issueA = [&](int kc, int buf) {   // ASRC==1 only
        const __nv_bfloat16* gh = Abh + (size_t)(m0 + r) * lda + kc + h2 * 16;
        const __nv_bfloat16* gl = Abl + (size_t)(m0 + r) * lda + kc + h2 * 16;
        const uint32_t d = sb + (uint32_t)(buf * 40960) + r * 80 + h2 * 32;
        cpa16(d, gh);          cpa16(d + 16, gh + 8);
        cpa16(d + 10240, gl);  cpa16(d + 10240 + 16, gl + 8);
    };
    auto loadSplitA = [&](int kc) {        // ASRC==0, single A buffer
        const int kh = h2 * 16;
        const float4* gp = (const float4*)(Afp + (size_t)(m0 + r) * lda + kc + kh);
        char* rowH = smem + r * 80;
        char* rowL = smem + 10240 + r * 80;
        #pragma unroll
        for (int q = 0; q < 4; q++) {
            uint2 h, l;
            split4(gp[q], h, l);
            const int kk = kh + q * 4;
            *(uint2*)(rowH + kk * 2) = h;
            *(uint2*)(rowL + kk * 2) = l;
        }
    };

    const int NC = Kdim >> 5;
    if (ASRC) issueA(0, 0);
    issueB(0, 0);
    cpa_commit();

    for (int ic = 0; ic < NC; ic++) {
        const int buf = ic & 1;
        if (ic + 1 < NC) {
            if (ASRC) issueA((ic + 1) << 5, buf ^ 1);
            issueB((ic + 1) << 5, buf ^ 1);
        }
        cpa_commit();
        if (!ASRC) loadSplitA(ic << 5);
        cpa_wait<1>();
        __syncthreads();

        const uint32_t aH = sb + (ASRC ? (uint32_t)(buf * 40960) : 0u);
        const uint32_t aL = aH + 10240;
        const uint32_t bH = sb + (ASRC ? (uint32_t)(buf * 40960 + 20480)
                                       : (uint32_t)(20480 + buf * 20480));
        const uint32_t bL = bH + 10240;

        // per k-half: load Ah,Bh -> mma; load Al -> mma; load Bl -> mma
        #pragma unroll
        for (int kh2 = 0; kh2 < 2; kh2++) {
            uint32_t ah[4][4], al[4][4], bh[4][2], bl[4][2];
            const int cA = kh2 * 2 + ((lane >> 4) & 1);
            const int cB = kh2 * 2 + ((lane >> 3) & 1);
            #pragma unroll
            for (int mt = 0; mt < 4; mt++) {
                const int row = wm + mt * 16 + (lane & 15);
                ldsm_x4(aH + row * 80 + cA * 16,
                        ah[mt][0], ah[mt][1], ah[mt][2], ah[mt][3]);
            }
            #pragma unroll
            for (int p = 0; p < 2; p++) {
                const int row = wn + p * 16 + ((lane >> 4) & 1) * 8 + (lane & 7);
                uint32_t r0, r1, r2, r3;
                ldsm_x4(bH + row * 80 + cB * 16, r0, r1, r2, r3);
                bh[p * 2][0] = r0; bh[p * 2][1] = r1;
                bh[p * 2 + 1][0] = r2; bh[p * 2 + 1][1] = r3;
            }
            // prefetch Al while Ah*Bh issues
            #pragma unroll
            for (int mt = 0; mt < 4; mt++) {
                const int row = wm + mt * 16 + (lane & 15);
                ldsm_x4(aL + row * 80 + cA * 16,
                        al[mt][0], al[mt][1], al[mt][2], al[mt][3]);
            }
            #pragma unroll
            for (int mt = 0; mt < 4; mt++)
                #pragma unroll
                for (int nt = 0; nt < 4; nt++)
                    mma16816(acc[mt][nt], ah[mt], bh[nt]);
            // prefetch Bl while Al*Bh issues
            #pragma unroll
            for (int p = 0; p < 2; p++) {
                const int row = wn + p * 16 + ((lane >> 4) & 1) * 8 + (lane & 7);
                uint32_t r0, r1, r2, r3;
                ldsm_x4(bL + row * 80 + cB * 16, r0, r1, r2, r3);
                bl[p * 2][0] = r0; bl[p * 2][1] = r1;
                bl[p * 2 + 1][0] = r2; bl[p * 2 + 1][1] = r3;
            }
            #pragma unroll
            for (int mt = 0; mt < 4; mt++)
                #pragma unroll
                for (int nt = 0; nt < 4; nt++)
                    mma16816(acc[mt][nt], al[mt], bh[nt]);
            #pragma unroll
            for (int mt = 0; mt < 4; mt++)
                #pragma unroll
                for (int nt = 0; nt < 4; nt++)
                    mma16816(acc[mt][nt], ah[mt], bl[nt]);
        }
        __syncthreads();
    }

    // ---- epilogue ----
    #pragma unroll
    for (int mt = 0; mt < 4; mt++) {
        #pragma unroll
        for (int nt = 0; nt < 4; nt++) {
            const int col = n0 + wn + nt * 8 + (lane & 3) * 2;
            const int row0 = m0 + wm + mt * 16 + (lane >> 2);
            float2 bb = *(const float2*)(bias + col);
            const float v00 = acc[mt][nt][0] + bb.x;
            const float v01 = acc[mt][nt][1] + bb.y;
            const float v10 = acc[mt][nt][2] + bb.x;
            const float v11 = acc[mt][nt][3] + bb.y;
            if (MODE == 0) {
                if (col < 256) {
                    *(float2*)&d_ts[(size_t)row0 * DIN + col] = make_float2(v00, v01);
                    *(float2*)&d_ts[(size_t)(row0 + 8) * DIN + col] = make_float2(v10, v11);
                } else {
                    outstore(row0, col - 256, v00, v01);
                    outstore(row0 + 8, col - 256, v10, v11);
                }
            } else if (MODE == 1) {
                outstore(row0, col + 256, v00, v01);
                outstore(row0 + 8, col + 256, v10, v11);
            } else {
                float2 sc = *(const float2*)(d_scale + col);
                float2 sh = *(const float2*)(d_shift + col);
                float2 o0 = *(const float2*)&d_outcat[(size_t)row0 * DCAT + col];
                float2 o1 = *(const float2*)&d_outcat[(size_t)(row0 + 8) * DCAT + col];
                float2 w0, w1;
                w0.x = fmaxf(v00, 0.f) * fmaxf(fmaf(o0.x, sc.x, sh.x), 0.f);
                w0.y = fmaxf(v01, 0.f) * fmaxf(fmaf(o0.y, sc.y, sh.y), 0.f);
                w1.x = fmaxf(v10, 0.f) * fmaxf(fmaf(o1.x, sc.x, sh.x), 0.f);
                w1.y = fmaxf(v11, 0.f) * fmaxf(fmaf(o1.y, sc.y, sh.y), 0.f);
                *(float2*)(Cout + (size_t)row0 * DCAT + col) = w0;
                *(float2*)(Cout + (size_t)(row0 + 8) * DCAT + col) = w1;
            }
        }
    }
}

// ---------------- attention: cp.async tile, smem energies ----------------
__global__ __launch_bounds__(256) void attn_kernel(
    const float* __restrict__ x, const float* __restrict__ nb)
{
    __shared__ __align__(16) float Xs[KNB * DIN];   // 32 KB
    __shared__ float es[KNB], sx[KNB], att[KNB];
    __shared__ float red[8];

    const int n = blockIdx.x;
    const int t = threadIdx.x;
    const int w = t >> 5, l = t & 31;

    // async copy the 32KB neighbor tile straight to smem (no register round-trip)
    const uint32_t xsb = smem_u32(Xs);
    const char* src = (const char*)(nb + (size_t)n * KNB * DIN);
    #pragma unroll
    for (int j = 0; j < 8; j++)
        cpa16(xsb + (uint32_t)(t + j * 256) * 16, src + (size_t)(t + j * 256) * 16);
    cpa_commit();

    // ts slice this lane needs (coalesced per j)
    float tsr[8];
    #pragma unroll
    for (int j = 0; j < 8; j++) tsr[j] = d_ts[(size_t)n * DIN + l + 32 * j];

    // ebias partial
    float eb = x[(size_t)n * DIN + t] * d_v[t];
    #pragma unroll
    for (int off = 16; off > 0; off >>= 1) eb += __shfl_down_sync(0xffffffffu, eb, off);
    if (l == 0) red[w] = eb;

    cpa_wait<0>();
    __syncthreads();

    // energies + row sums: warp w owns rows 4w..4w+3
    #pragma unroll
    for (int rr = 0; rr < 4; rr++) {
        const int k = 4 * w + rr;
        const float* xr = &Xs[k * DIN];
        float e = 0.f, s = 0.f;
        #pragma unroll
        for (int j = 0; j < 8; j++) {
            const float vx = xr[l + 32 * j];
            e = fmaf(vx, tsr[j], e);
            s += vx;
        }
        #pragma unroll
        for (int off = 16; off > 0; off >>= 1) {
            e += __shfl_down_sync(0xffffffffu, e, off);
            s += __shfl_down_sync(0xffffffffu, s, off);
        }
        if (l == 0) { es[k] = e; sx[k] = s; }
    }
    __syncthreads();

    if (w == 0) {
        float v = (l < 8) ? red[l] : 0.f;
        #pragma unroll
        for (int off = 16; off > 0; off >>= 1) v += __shfl_xor_sync(0xffffffffu, v, off);
        const float s_eb = v + d_c0[0];
        float e = (sx[l] == 0.0f) ? 1e-12f : (es[l] + s_eb);
        float m = e;
        #pragma unroll
        for (int off = 16; off > 0; off >>= 1) m = fmaxf(m, __shfl_xor_sync(0xffffffffu, m, off));
        float p = __expf(e - m);
        float s = p;
        #pragma unroll
        for (int off = 16; off > 0; off >>= 1) s += __shfl_xor_sync(0xffffffffu, s, off);
        att[l] = p / s;
    }
    __syncthreads();

    float accv = 0.f;
    #pragma unroll
    for (int k = 0; k < KNB; k++) accv = fmaf(att[k], Xs[k * DIN + t], accv);

    __nv_bfloat16 h = __float2bfloat16(accv);
    d_ch[(size_t)n * DIN + t] = h;
    d_cl[(size_t)n * DIN + t] = __float2bfloat16(accv - __bfloat162float(h));
}

// ---------------- BN: deterministic two-pass ----------------
__global__ void bn_reduce_kernel()
{
    const int t = threadIdx.x;
    const int b = blockIdx.x;
    float s0 = 0.f, q0 = 0.f, s1 = 0.f, q1 = 0.f;
    for (int r = 0; r < 128; r++) {
        size_t row = (size_t)(b * 128 + r);
        float v0 = d_outcat[row * DCAT + t];
        float v1 = d_outcat[row * DCAT + t + 256];
        s0 += v0; q0 = fmaf(v0, v0, q0);
        s1 += v1; q1 = fmaf(v1, v1, q1);
    }
    d_part[b * 1024 + t]       = s0;
    d_part[b * 1024 + t + 256] = s1;
    d_part[b * 1024 + 512 + t]       = q0;
    d_part[b * 1024 + 512 + t + 256] = q1;
}

__global__ void bn_finalize_kernel(const float* __restrict__ gamma,
                                   const float* __restrict__ beta)
{
    const int c = blockIdx.x * 256 + threadIdx.x;
    float s = 0.f, q = 0.f;
    for (int p = 0; p < 128; p++) {
        s += d_part[p * 1024 + c];
        q += d_part[p * 1024 + 512 + c];
    }
    const float invN = 1.0f / (float)N_NODES;
    float mean = s * invN;
    float var  = q * invN - mean * mean;
    float inv  = rsqrtf(var + EPSBN);
    float scl  = gamma[c] * inv;
    d_scale[c] = scl;
    d_shift[c] = beta[c] - mean * scl;
}

// ---------------- launch ----------------
extern "C" void kernel_launch(void* const* d_in, const int* in_sizes, int n_in,
                              void* d_out, int out_size)
{
    const float* x    = (const float*)d_in[0];
    const float* nb   = (const float*)d_in[1];
    const float* Wq   = (const float*)d_in[2];
    const float* bq   = (const float*)d_in[3];
    const float* Wk   = (const float*)d_in[4];
    const float* bk   = (const float*)d_in[5];
    const float* Wv   = (const float*)d_in[6];
    const float* bv   = (const float*)d_in[7];
    const float* Wno  = (const float*)d_in[8];
    const float* bno  = (const float*)d_in[9];
    const float* Wio  = (const float*)d_in[10];
    const float* bio  = (const float*)d_in[11];
    const float* Wg   = (const float*)d_in[12];
    const float* bg   = (const float*)d_in[13];
    const float* gamma= (const float*)d_in[14];
    const float* beta = (const float*)d_in[15];
    float* out = (float*)d_out;

    void *pB12h, *pB12l, *pB3h, *pB3l, *pB4h, *pB4l;
    void *pch, *pcl, *poch, *pocl, *pbias12, *pb2;
    cudaGetSymbolAddress(&pB12h, d_B12h);
    cudaGetSymbolAddress(&pB12l, d_B12l);
    cudaGetSymbolAddress(&pB3h,  d_B3h);
    cudaGetSymbolAddress(&pB3l,  d_B3l);
    cudaGetSymbolAddress(&pB4h,  d_B4h);
    cudaGetSymbolAddress(&pB4l,  d_B4l);
    cudaGetSymbolAddress(&pch,   d_ch);
    cudaGetSymbolAddress(&pcl,   d_cl);
    cudaGetSymbolAddress(&poch,  d_och);
    cudaGetSymbolAddress(&pocl,  d_ocl);
    cudaGetSymbolAddress(&pbias12, d_bias12);
    cudaGetSymbolAddress(&pb2,     d_b2);

    cudaFuncSetAttribute(tc_gemm<0, 0>, cudaFuncAttributeMaxDynamicSharedMemorySize, 61440);
    cudaFuncSetAttribute(tc_gemm<1, 1>, cudaFuncAttributeMaxDynamicSharedMemorySize, 81920);
    cudaFuncSetAttribute(tc_gemm<1, 2>, cudaFuncAttributeMaxDynamicSharedMemorySize, 81920);

    precompute_kernel<<<dim3(256, 3), 256>>>(Wq, bq, Wk, bk, Wv, bv, Wno, bno, bio);
    split_weights_kernel<<<dim3(512, 3), 256>>>(Wio, Wg);

    // G12: [ts | self_out] = x @ [M;Wio]^T + [tb|bio]
    tc_gemm<0, 0><<<dim3(4, 128), 256, 61440>>>(
        x, nullptr, nullptr, DIN,
        (const __nv_bfloat16*)pB12h, (const __nv_bfloat16*)pB12l,
        (const float*)pbias12, nullptr, DIN);

    // attention -> c (bf16 hi/lo)
    attn_kernel<<<N_NODES, 256>>>(x, nb);

    // G3: neigh_out = c @ W2^T + b2 -> outcat[:,256:512]
    tc_gemm<1, 1><<<dim3(2, 128), 256, 81920>>>(
        nullptr, (const __nv_bfloat16*)pch, (const __nv_bfloat16*)pcl, DIN,
        (const __nv_bfloat16*)pB3h, (const __nv_bfloat16*)pB3l,
        (const float*)pb2, nullptr, DIN);

    bn_reduce_kernel<<<128, 256>>>();
    bn_finalize_kernel<<<2, 256>>>(gamma, beta);

    // G4: gate GEMM + fused BN/gate epilogue -> d_out
    tc_gemm<1, 2><<<dim3(4, 128), 256, 81920>>>(
        nullptr, (const __nv_bfloat16*)poch, (const __nv_bfloat16*)pocl, DCAT,
        (const __nv_bfloat16*)pB4h, (const __nv_bfloat16*)pB4l,
        bg, out, DCAT);
}